// round 4
// baseline (speedup 1.0000x reference)
#include <cuda_runtime.h>
#include <cuda_bf16.h>
#include <cstdint>

#define Tn 512
#define Bn 128
#define Hn 1024
#define Vn 256
#define En 512
#define SCAN_CTAS 128

typedef __nv_bfloat16 bf16;

// ------------------------- scratch (static device memory; no allocs) ----
__device__ bf16  g_h1_hi[(size_t)Tn * Bn * Hn];
__device__ bf16  g_h1_lo[(size_t)Tn * Bn * Hn];
__device__ bf16  g_h2_hi[(size_t)Tn * Bn * Hn];
__device__ bf16  g_h2_lo[(size_t)Tn * Bn * Hn];
__device__ bf16  g_nm_hi[(size_t)Tn * Bn * Hn];
__device__ bf16  g_nm_lo[(size_t)Tn * Bn * Hn];
__device__ float g_xp1 [(size_t)Tn * Bn * Hn];
__device__ float g_xpe [Vn * Hn];
__device__ bf16  g_wh0h[Hn * Hn], g_wh0l[Hn * Hn];
__device__ bf16  g_wh1h[Hn * Hn], g_wh1l[Hn * Hn];
__device__ bf16  g_wi1h[Hn * Hn], g_wi1l[Hn * Hn];
__device__ bf16  g_pwh [Vn * Hn], g_pwl [Vn * Hn];

// grid-barrier state (generation-based; safe across launches/replays)
__device__ unsigned g_bar_cnt = 0;
__device__ unsigned g_bar_gen = 0;

// ------------------------- helpers --------------------------------------
__device__ __forceinline__ void mma_bf16(float* c,
    uint32_t a0, uint32_t a1, uint32_t a2, uint32_t a3,
    uint32_t b0, uint32_t b1)
{
    asm volatile(
        "mma.sync.aligned.m16n8k16.row.col.f32.bf16.bf16.f32 "
        "{%0,%1,%2,%3}, {%4,%5,%6,%7}, {%8,%9}, {%0,%1,%2,%3};\n"
        : "+f"(c[0]), "+f"(c[1]), "+f"(c[2]), "+f"(c[3])
        : "r"(a0), "r"(a1), "r"(a2), "r"(a3), "r"(b0), "r"(b1));
}

__device__ __forceinline__ uint32_t ldsm32(const bf16* p) {
    return *reinterpret_cast<const uint32_t*>(p);
}

// ------------------------- weight splitting (fp32 -> bf16 hi/lo) --------
__global__ void split_kernel(const float* __restrict__ src,
                             bf16* __restrict__ hi, bf16* __restrict__ lo, int n)
{
    int i = blockIdx.x * 256 + threadIdx.x;
    if (i < n) {
        float v = src[i];
        bf16 h = __float2bfloat16(v);
        hi[i] = h;
        lo[i] = __float2bfloat16(v - __bfloat162float(h));
    }
}

// ------------------------- xpe[v][h] = Wi0 @ emb[v] + bi0 (fp32) --------
__global__ void __launch_bounds__(256) xpe_kernel(
    const float* __restrict__ emb, const float* __restrict__ wi0,
    const float* __restrict__ bi0, float* __restrict__ xpe)
{
    __shared__ float se[16][33];
    __shared__ float sw[64][33];
    int vbase = blockIdx.x * 16, hbase = blockIdx.y * 64;
    int tid = threadIdx.x;
    int vl = tid >> 4;
    int hl = (tid & 15) * 4;
    float acc[4] = {0.f, 0.f, 0.f, 0.f};
    for (int k0 = 0; k0 < En; k0 += 32) {
        for (int i = tid; i < 16 * 32; i += 256)
            se[i >> 5][i & 31] = emb[(size_t)(vbase + (i >> 5)) * En + k0 + (i & 31)];
        for (int i = tid; i < 64 * 32; i += 256)
            sw[i >> 5][i & 31] = wi0[(size_t)(hbase + (i >> 5)) * En + k0 + (i & 31)];
        __syncthreads();
#pragma unroll
        for (int kk = 0; kk < 32; kk++) {
            float a = se[vl][kk];
            acc[0] += a * sw[hl + 0][kk];
            acc[1] += a * sw[hl + 1][kk];
            acc[2] += a * sw[hl + 2][kk];
            acc[3] += a * sw[hl + 3][kk];
        }
        __syncthreads();
    }
#pragma unroll
    for (int p = 0; p < 4; p++)
        xpe[(size_t)(vbase + vl) * Hn + hbase + hl + p] = acc[p] + bi0[hbase + hl + p];
}

// ------------------------- persistent scan ------------------------------
// One launch runs all T steps. 128 CTAs: blockIdx.x -> 32-wide N tile (32 of
// them), blockIdx.y -> 32-row M tile (4 of them). W tile (32 x 1024, hi+lo)
// lives in SMEM for the whole kernel. Grid barrier between steps.
//
// SMEM layout (bf16 elements):
//   sWh: 16 chunks x [32][72]   = 36864
//   sWl: 16 chunks x [32][72]   = 36864
//   sAh: 2 bufs x [32][72]      =  4608
//   sAl: 2 bufs x [32][72]      =  4608
// total 82944 el = 165888 bytes
#define SCAN_SMEM_BYTES (82944 * 2)

__global__ void __launch_bounds__(256, 1) scan_persist_kernel(
    const bf16* __restrict__ Whi, const bf16* __restrict__ Wlo,
    bf16* __restrict__ hseq_hi, bf16* __restrict__ hseq_lo,
    const float* __restrict__ xp, const int* __restrict__ x, int layer)
{
    extern __shared__ bf16 smem[];
    bf16* sWh = smem;
    bf16* sWl = sWh + 16 * 32 * 72;
    bf16* sAh = sWl + 16 * 32 * 72;
    bf16* sAl = sAh + 2 * 32 * 72;

    int tid = threadIdx.x, lane = tid & 31, warp = tid >> 5;
    int wm = warp & 1, wn = warp >> 1;              // 2 x 4 warp grid
    int mbase = blockIdx.y * 32, nbase = blockIdx.x * 32;
    int g = lane >> 2, tq = lane & 3;

    // ---- load W tile once: rows nbase..nbase+31, all K, hi+lo ----
    for (int i = tid; i < 32 * 128; i += 256) {       // 128 uint4 per row
        int r = i >> 7;
        int kc = (i & 127) * 8;
        int ch = kc >> 6, kk = kc & 63;
        *reinterpret_cast<uint4*>(&sWh[ch * 2304 + r * 72 + kk]) =
            *reinterpret_cast<const uint4*>(Whi + (size_t)(nbase + r) * Hn + kc);
        *reinterpret_cast<uint4*>(&sWl[ch * 2304 + r * 72 + kk]) =
            *reinterpret_cast<const uint4*>(Wlo + (size_t)(nbase + r) * Hn + kc);
    }
    __syncthreads();

    unsigned my_gen = 0;
    if (tid == 0) my_gen = atomicAdd(&g_bar_gen, 0u);

    int st_r = tid >> 3;                 // staging: row 0..31
    int st_k = (tid & 7) * 8;            // staging: col 0..56

    for (int t = 0; t < Tn; t++) {
        float acc[4] = {0.f, 0.f, 0.f, 0.f};

        if (t > 0) {
            const bf16* hp_hi = hseq_hi + (size_t)(t - 1) * Bn * Hn;
            const bf16* hp_lo = hseq_lo + (size_t)(t - 1) * Bn * Hn;
            // stage chunk 0 into buf 0
            *reinterpret_cast<uint4*>(&sAh[st_r * 72 + st_k]) =
                *reinterpret_cast<const uint4*>(hp_hi + (size_t)(mbase + st_r) * Hn + st_k);
            *reinterpret_cast<uint4*>(&sAl[st_r * 72 + st_k]) =
                *reinterpret_cast<const uint4*>(hp_lo + (size_t)(mbase + st_r) * Hn + st_k);
            __syncthreads();

            for (int ch = 0; ch < 16; ch++) {
                int cur = ch & 1;
                if (ch < 15) {          // prefetch next chunk into other buffer
                    int nb = cur ^ 1;
                    int kbase = (ch + 1) * 64 + st_k;
                    *reinterpret_cast<uint4*>(&sAh[nb * 2304 + st_r * 72 + st_k]) =
                        *reinterpret_cast<const uint4*>(hp_hi + (size_t)(mbase + st_r) * Hn + kbase);
                    *reinterpret_cast<uint4*>(&sAl[nb * 2304 + st_r * 72 + st_k]) =
                        *reinterpret_cast<const uint4*>(hp_lo + (size_t)(mbase + st_r) * Hn + kbase);
                }
                const bf16* Ah = sAh + cur * 2304;
                const bf16* Al = sAl + cur * 2304;
                const bf16* Wh = sWh + ch * 2304;
                const bf16* Wl = sWl + ch * 2304;
                int ar = wm * 16 + g;
                int br = wn * 8 + g;
#pragma unroll
                for (int kk = 0; kk < 64; kk += 16) {
                    uint32_t ah0 = ldsm32(&Ah[ar * 72 + kk + 2 * tq]);
                    uint32_t ah1 = ldsm32(&Ah[(ar + 8) * 72 + kk + 2 * tq]);
                    uint32_t ah2 = ldsm32(&Ah[ar * 72 + kk + 2 * tq + 8]);
                    uint32_t ah3 = ldsm32(&Ah[(ar + 8) * 72 + kk + 2 * tq + 8]);
                    uint32_t al0 = ldsm32(&Al[ar * 72 + kk + 2 * tq]);
                    uint32_t al1 = ldsm32(&Al[(ar + 8) * 72 + kk + 2 * tq]);
                    uint32_t al2 = ldsm32(&Al[ar * 72 + kk + 2 * tq + 8]);
                    uint32_t al3 = ldsm32(&Al[(ar + 8) * 72 + kk + 2 * tq + 8]);
                    uint32_t bh0 = ldsm32(&Wh[br * 72 + kk + 2 * tq]);
                    uint32_t bh1 = ldsm32(&Wh[br * 72 + kk + 2 * tq + 8]);
                    uint32_t bl0 = ldsm32(&Wl[br * 72 + kk + 2 * tq]);
                    uint32_t bl1 = ldsm32(&Wl[br * 72 + kk + 2 * tq + 8]);
                    mma_bf16(acc, ah0, ah1, ah2, ah3, bh0, bh1);
                    mma_bf16(acc, ah0, ah1, ah2, ah3, bl0, bl1);
                    mma_bf16(acc, al0, al1, al2, al3, bh0, bh1);
                }
                __syncthreads();
            }
        }

        // ---- epilogue: add xp, tanh, split, store h_t ----
        bf16* out_hi = hseq_hi + (size_t)t * Bn * Hn;
        bf16* out_lo = hseq_lo + (size_t)t * Bn * Hn;
#pragma unroll
        for (int rh = 0; rh < 2; rh++) {
            int b = mbase + wm * 16 + g + rh * 8;
            int n = nbase + wn * 8 + 2 * tq;
            float xv0, xv1;
            if (layer == 0) {
                int xi = x[(size_t)b * Tn + t];
                xv0 = xp[(size_t)xi * Hn + n];
                xv1 = xp[(size_t)xi * Hn + n + 1];
            } else {
                const float* p = xp + ((size_t)t * Bn + b) * Hn + n;
                xv0 = p[0];
                xv1 = p[1];
            }
            float v0 = tanhf(acc[rh * 2 + 0] + xv0);
            float v1 = tanhf(acc[rh * 2 + 1] + xv1);
            bf16 h0 = __float2bfloat16(v0);
            bf16 l0 = __float2bfloat16(v0 - __bfloat162float(h0));
            bf16 h1 = __float2bfloat16(v1);
            bf16 l1 = __float2bfloat16(v1 - __bfloat162float(h1));
            __nv_bfloat162 ph; ph.x = h0; ph.y = h1;
            __nv_bfloat162 pl; pl.x = l0; pl.y = l1;
            size_t o = (size_t)b * Hn + n;
            *reinterpret_cast<__nv_bfloat162*>(out_hi + o) = ph;
            *reinterpret_cast<__nv_bfloat162*>(out_lo + o) = pl;
        }

        // ---- grid barrier ----
        __threadfence();
        __syncthreads();
        if (tid == 0) {
            if (atomicAdd(&g_bar_cnt, 1u) == SCAN_CTAS - 1u) {
                atomicExch(&g_bar_cnt, 0u);
                __threadfence();
                atomicExch(&g_bar_gen, my_gen + 1u);
            } else {
                while (atomicAdd(&g_bar_gen, 0u) != my_gen + 1u) {
                    __nanosleep(40);
                }
            }
            my_gen++;
        }
        __syncthreads();
    }
}

// ------------------------- big parallel GEMM (split-bf16 x3) ------------
// C[m,n] = A[m,:] . W[n,:] + bias[n]
// mode 0: out fp32 row-major, N=1024 (xproj layer 2)
// mode 1: out logits: m = t*128+b -> out[(b*T+t)*256 + n], N=256
__global__ void __launch_bounds__(256) gemm_split_kernel(
    const bf16* __restrict__ Ahi, const bf16* __restrict__ Alo,
    const bf16* __restrict__ Whi, const bf16* __restrict__ Wlo,
    const float* __restrict__ bias, float* __restrict__ outf, int mode)
{
    __shared__ bf16 sAh[64][72], sAl[64][72], sWh[64][72], sWl[64][72];
    int tid = threadIdx.x, lane = tid & 31, warp = tid >> 5;
    int wm = warp & 3, wn = warp >> 2;           // 4 x 2 warp grid
    int mbase = blockIdx.x * 64, nbase = blockIdx.y * 64;
    int g = lane >> 2, tq = lane & 3;
    float c[4][4] = {};

    for (int k0 = 0; k0 < Hn; k0 += 64) {
#pragma unroll
        for (int i = 0; i < 2; i++) {
            int idx = tid + i * 256;
            int r = idx >> 3, c4 = (idx & 7) * 8;
            *reinterpret_cast<uint4*>(&sAh[r][c4]) =
                *reinterpret_cast<const uint4*>(Ahi + (size_t)(mbase + r) * Hn + k0 + c4);
            *reinterpret_cast<uint4*>(&sAl[r][c4]) =
                *reinterpret_cast<const uint4*>(Alo + (size_t)(mbase + r) * Hn + k0 + c4);
            *reinterpret_cast<uint4*>(&sWh[r][c4]) =
                *reinterpret_cast<const uint4*>(Whi + (size_t)(nbase + r) * Hn + k0 + c4);
            *reinterpret_cast<uint4*>(&sWl[r][c4]) =
                *reinterpret_cast<const uint4*>(Wlo + (size_t)(nbase + r) * Hn + k0 + c4);
        }
        __syncthreads();
#pragma unroll
        for (int kk = 0; kk < 64; kk += 16) {
            int ar = wm * 16 + g;
            uint32_t ah0 = ldsm32(&sAh[ar][kk + 2 * tq]);
            uint32_t ah1 = ldsm32(&sAh[ar + 8][kk + 2 * tq]);
            uint32_t ah2 = ldsm32(&sAh[ar][kk + 2 * tq + 8]);
            uint32_t ah3 = ldsm32(&sAh[ar + 8][kk + 2 * tq + 8]);
            uint32_t al0 = ldsm32(&sAl[ar][kk + 2 * tq]);
            uint32_t al1 = ldsm32(&sAl[ar + 8][kk + 2 * tq]);
            uint32_t al2 = ldsm32(&sAl[ar][kk + 2 * tq + 8]);
            uint32_t al3 = ldsm32(&sAl[ar + 8][kk + 2 * tq + 8]);
#pragma unroll
            for (int j = 0; j < 4; j++) {
                int br = wn * 32 + j * 8 + g;
                uint32_t bh0 = ldsm32(&sWh[br][kk + 2 * tq]);
                uint32_t bh1 = ldsm32(&sWh[br][kk + 2 * tq + 8]);
                uint32_t bl0 = ldsm32(&sWl[br][kk + 2 * tq]);
                uint32_t bl1 = ldsm32(&sWl[br][kk + 2 * tq + 8]);
                mma_bf16(c[j], ah0, ah1, ah2, ah3, bh0, bh1);
                mma_bf16(c[j], ah0, ah1, ah2, ah3, bl0, bl1);
                mma_bf16(c[j], al0, al1, al2, al3, bh0, bh1);
            }
        }
        __syncthreads();
    }

#pragma unroll
    for (int j = 0; j < 4; j++) {
#pragma unroll
        for (int rh = 0; rh < 2; rh++) {
            int m = mbase + wm * 16 + g + rh * 8;
            int n = nbase + wn * 32 + j * 8 + 2 * tq;
            float v0 = c[j][rh * 2 + 0] + bias[n];
            float v1 = c[j][rh * 2 + 1] + bias[n + 1];
            if (mode == 0) {
                outf[(size_t)m * Hn + n] = v0;
                outf[(size_t)m * Hn + n + 1] = v1;
            } else {
                int b = m & (Bn - 1), t = m >> 7;
                size_t o = ((size_t)b * Tn + t) * Vn + n;
                outf[o] = v0;
                outf[o + 1] = v1;
            }
        }
    }
}

// ------------------------- layernorm + split ----------------------------
__global__ void __launch_bounds__(256) ln_kernel(
    const bf16* __restrict__ hhi, const bf16* __restrict__ hlo,
    const float* __restrict__ gam, const float* __restrict__ bet,
    bf16* __restrict__ nhi, bf16* __restrict__ nlo)
{
    __shared__ float red[18];
    size_t row = blockIdx.x;
    int tid = threadIdx.x;
    const bf16* ph = hhi + row * Hn;
    const bf16* pl = hlo + row * Hn;
    int c0 = tid * 4;
    float v[4];
    float s = 0.f, q = 0.f;
#pragma unroll
    for (int i = 0; i < 4; i++) {
        v[i] = __bfloat162float(ph[c0 + i]) + __bfloat162float(pl[c0 + i]);
        s += v[i];
        q += v[i] * v[i];
    }
#pragma unroll
    for (int o = 16; o; o >>= 1) {
        s += __shfl_xor_sync(0xffffffffu, s, o);
        q += __shfl_xor_sync(0xffffffffu, q, o);
    }
    int warp = tid >> 5, lane = tid & 31;
    if (lane == 0) { red[warp] = s; red[warp + 8] = q; }
    __syncthreads();
    if (tid == 0) {
        float ss = 0.f, qq = 0.f;
#pragma unroll
        for (int i = 0; i < 8; i++) { ss += red[i]; qq += red[i + 8]; }
        float mu = ss / (float)Hn;
        float var = qq / (float)Hn - mu * mu;
        red[16] = mu;
        red[17] = rsqrtf(var + 1e-5f);
    }
    __syncthreads();
    float mu = red[16], rstd = red[17];
#pragma unroll
    for (int i = 0; i < 4; i++) {
        float nv = (v[i] - mu) * rstd * gam[c0 + i] + bet[c0 + i];
        bf16 h = __float2bfloat16(nv);
        nhi[row * Hn + c0 + i] = h;
        nlo[row * Hn + c0 + i] = __float2bfloat16(nv - __bfloat162float(h));
    }
}

// ------------------------- launch ---------------------------------------
extern "C" void kernel_launch(void* const* d_in, const int* in_sizes, int n_in,
                              void* d_out, int out_size)
{
    const float* emb    = (const float*)d_in[0];
    const float* wi0    = (const float*)d_in[1];
    const float* bi0    = (const float*)d_in[2];
    const float* wh0    = (const float*)d_in[3];
    const float* wi1    = (const float*)d_in[4];
    const float* bi1    = (const float*)d_in[5];
    const float* wh1    = (const float*)d_in[6];
    const float* ln_g   = (const float*)d_in[7];
    const float* ln_b   = (const float*)d_in[8];
    const float* proj_w = (const float*)d_in[9];
    const float* proj_b = (const float*)d_in[10];
    const int*   x      = (const int*)d_in[11];

    bf16 *h1h, *h1l, *h2h, *h2l, *nmh, *nml;
    bf16 *wh0h, *wh0l, *wh1h, *wh1l, *wi1h, *wi1l, *pwh, *pwl;
    float *xp1, *xpe;
    cudaGetSymbolAddress((void**)&h1h,  g_h1_hi);
    cudaGetSymbolAddress((void**)&h1l,  g_h1_lo);
    cudaGetSymbolAddress((void**)&h2h,  g_h2_hi);
    cudaGetSymbolAddress((void**)&h2l,  g_h2_lo);
    cudaGetSymbolAddress((void**)&nmh,  g_nm_hi);
    cudaGetSymbolAddress((void**)&nml,  g_nm_lo);
    cudaGetSymbolAddress((void**)&wh0h, g_wh0h);
    cudaGetSymbolAddress((void**)&wh0l, g_wh0l);
    cudaGetSymbolAddress((void**)&wh1h, g_wh1h);
    cudaGetSymbolAddress((void**)&wh1l, g_wh1l);
    cudaGetSymbolAddress((void**)&wi1h, g_wi1h);
    cudaGetSymbolAddress((void**)&wi1l, g_wi1l);
    cudaGetSymbolAddress((void**)&pwh,  g_pwh);
    cudaGetSymbolAddress((void**)&pwl,  g_pwl);
    cudaGetSymbolAddress((void**)&xp1,  g_xp1);
    cudaGetSymbolAddress((void**)&xpe,  g_xpe);

    cudaFuncSetAttribute(scan_persist_kernel,
                         cudaFuncAttributeMaxDynamicSharedMemorySize,
                         SCAN_SMEM_BYTES);

    // 1) split weights into bf16 hi/lo pairs
    split_kernel<<<(Hn * Hn + 255) / 256, 256>>>(wh0, wh0h, wh0l, Hn * Hn);
    split_kernel<<<(Hn * Hn + 255) / 256, 256>>>(wh1, wh1h, wh1l, Hn * Hn);
    split_kernel<<<(Hn * Hn + 255) / 256, 256>>>(wi1, wi1h, wi1l, Hn * Hn);
    split_kernel<<<(Vn * Hn + 255) / 256, 256>>>(proj_w, pwh, pwl, Vn * Hn);

    // 2) per-vocab input projection table
    xpe_kernel<<<dim3(16, 16), 256>>>(emb, wi0, bi0, xpe);

    // 3) layer-1 scan (single persistent launch, all T steps)
    scan_persist_kernel<<<dim3(32, 4), 256, SCAN_SMEM_BYTES>>>(
        wh0h, wh0l, h1h, h1l, xpe, x, 0);

    // 4) layer-2 input projection: xp1 = h1 @ Wi1^T + bi1
    gemm_split_kernel<<<dim3(1024, 16), 256>>>(h1h, h1l, wi1h, wi1l, bi1, xp1, 0);

    // 5) layer-2 scan
    scan_persist_kernel<<<dim3(32, 4), 256, SCAN_SMEM_BYTES>>>(
        wh1h, wh1l, h2h, h2l, xp1, x, 1);

    // 6) layernorm
    ln_kernel<<<Tn * Bn, 256>>>(h2h, h2l, ln_g, ln_b, nmh, nml);

    // 7) output projection -> logits [B, T, 256]
    gemm_split_kernel<<<dim3(1024, 4), 256>>>(nmh, nml, pwh, pwl, proj_b, (float*)d_out, 1);
}

// round 5
// speedup vs baseline: 1.7977x; 1.7977x over previous
#include <cuda_runtime.h>
#include <cuda_bf16.h>
#include <cstdint>

#define Tn 512
#define Bn 128
#define Hn 1024
#define Vn 256
#define En 512
#define SCAN_CTAS 128
#define CH 2312   // chunk stride in bf16 elems: 32*72 + 8 (bank-skew pad)

typedef __nv_bfloat16 bf16;

// ------------------------- scratch (static device memory; no allocs) ----
__device__ bf16  g_h1_hi[(size_t)Tn * Bn * Hn];
__device__ bf16  g_h1_lo[(size_t)Tn * Bn * Hn];
__device__ bf16  g_h2_hi[(size_t)Tn * Bn * Hn];
__device__ bf16  g_h2_lo[(size_t)Tn * Bn * Hn];
__device__ bf16  g_nm_hi[(size_t)Tn * Bn * Hn];
__device__ bf16  g_nm_lo[(size_t)Tn * Bn * Hn];
__device__ float g_xp1 [(size_t)Tn * Bn * Hn];
__device__ float g_xpe [Vn * Hn];
__device__ bf16  g_wh0h[Hn * Hn], g_wh0l[Hn * Hn];
__device__ bf16  g_wh1h[Hn * Hn], g_wh1l[Hn * Hn];
__device__ bf16  g_wi1h[Hn * Hn], g_wi1l[Hn * Hn];
__device__ bf16  g_pwh [Vn * Hn], g_pwl [Vn * Hn];

// grid-barrier state: monotonic counters, no reset -> no race, replay-safe
__device__ unsigned g_bar_cnt = 0;
__device__ unsigned g_bar_gen = 0;

// ------------------------- helpers --------------------------------------
__device__ __forceinline__ void mma_bf16(float* c,
    uint32_t a0, uint32_t a1, uint32_t a2, uint32_t a3,
    uint32_t b0, uint32_t b1)
{
    asm volatile(
        "mma.sync.aligned.m16n8k16.row.col.f32.bf16.bf16.f32 "
        "{%0,%1,%2,%3}, {%4,%5,%6,%7}, {%8,%9}, {%0,%1,%2,%3};\n"
        : "+f"(c[0]), "+f"(c[1]), "+f"(c[2]), "+f"(c[3])
        : "r"(a0), "r"(a1), "r"(a2), "r"(a3), "r"(b0), "r"(b1));
}

__device__ __forceinline__ uint32_t ldsm32(const bf16* p) {
    return *reinterpret_cast<const uint32_t*>(p);
}

// ------------------------- weight splitting (fp32 -> bf16 hi/lo) --------
__global__ void split_kernel(const float* __restrict__ src,
                             bf16* __restrict__ hi, bf16* __restrict__ lo, int n)
{
    int i = blockIdx.x * 256 + threadIdx.x;
    if (i < n) {
        float v = src[i];
        bf16 h = __float2bfloat16(v);
        hi[i] = h;
        lo[i] = __float2bfloat16(v - __bfloat162float(h));
    }
}

// ------------------------- xpe[v][h] = Wi0 @ emb[v] + bi0 (fp32) --------
__global__ void __launch_bounds__(256) xpe_kernel(
    const float* __restrict__ emb, const float* __restrict__ wi0,
    const float* __restrict__ bi0, float* __restrict__ xpe)
{
    __shared__ float se[16][33];
    __shared__ float sw[64][33];
    int vbase = blockIdx.x * 16, hbase = blockIdx.y * 64;
    int tid = threadIdx.x;
    int vl = tid >> 4;
    int hl = (tid & 15) * 4;
    float acc[4] = {0.f, 0.f, 0.f, 0.f};
    for (int k0 = 0; k0 < En; k0 += 32) {
        for (int i = tid; i < 16 * 32; i += 256)
            se[i >> 5][i & 31] = emb[(size_t)(vbase + (i >> 5)) * En + k0 + (i & 31)];
        for (int i = tid; i < 64 * 32; i += 256)
            sw[i >> 5][i & 31] = wi0[(size_t)(hbase + (i >> 5)) * En + k0 + (i & 31)];
        __syncthreads();
#pragma unroll
        for (int kk = 0; kk < 32; kk++) {
            float a = se[vl][kk];
            acc[0] += a * sw[hl + 0][kk];
            acc[1] += a * sw[hl + 1][kk];
            acc[2] += a * sw[hl + 2][kk];
            acc[3] += a * sw[hl + 3][kk];
        }
        __syncthreads();
    }
#pragma unroll
    for (int p = 0; p < 4; p++)
        xpe[(size_t)(vbase + vl) * Hn + hbase + hl + p] = acc[p] + bi0[hbase + hl + p];
}

// ------------------------- persistent scan ------------------------------
// 128 CTAs: blockIdx.x -> 32-wide N tile, blockIdx.y -> 32-row M tile.
// W tile (32 x 1024, hi+lo) SMEM-resident. Per step: A staged in two 512-wide
// K-halves; each of 8 warps computes the FULL 32x32 tile over its own 64-wide
// K-slice (K-split), partials reduced 8-way through SMEM. Grid barrier with
// non-serializing volatile-load polling.
//
// SMEM: W 32*CH*2B*2 = 147,968  A 16*CH*2B*2 wait: (16+16+8+8)*CH*2 = 221,952 B
#define SCAN_SMEM_BYTES (48 * CH * 2)

__global__ void __launch_bounds__(256, 1) scan_persist_kernel(
    const bf16* __restrict__ Whi, const bf16* __restrict__ Wlo,
    bf16* __restrict__ hseq_hi, bf16* __restrict__ hseq_lo,
    const float* __restrict__ xp, const int* __restrict__ x, int layer)
{
    extern __shared__ bf16 smem[];
    bf16* sWh = smem;                 // 16 chunks
    bf16* sWl = sWh + 16 * CH;        // 16 chunks
    bf16* sAh = sWl + 16 * CH;        // 8 chunks (one K-half)
    bf16* sAl = sAh + 8 * CH;         // 8 chunks
    float* sRed = reinterpret_cast<float*>(sAh);   // 8*1028 floats, reused

    int tid = threadIdx.x, lane = tid & 31, warp = tid >> 5;
    int g = lane >> 2, tq = lane & 3;
    int mbase = blockIdx.y * 32, nbase = blockIdx.x * 32;

    // ---- load W tile once (rows nbase..nbase+31, all K) ----
    for (int i = tid; i < 4096; i += 256) {
        int ch = i >> 8, rem = i & 255, r = rem >> 3, off = (rem & 7) * 8;
        *reinterpret_cast<uint4*>(&sWh[ch * CH + r * 72 + off]) =
            *reinterpret_cast<const uint4*>(Whi + (size_t)(nbase + r) * Hn + ch * 64 + off);
        *reinterpret_cast<uint4*>(&sWl[ch * CH + r * 72 + off]) =
            *reinterpret_cast<const uint4*>(Wlo + (size_t)(nbase + r) * Hn + ch * 64 + off);
    }
    __syncthreads();

    unsigned gen0 = 0;
    if (tid == 0) gen0 = *(volatile unsigned*)&g_bar_gen;

    int em = tid >> 3;               // epilogue/reduce row 0..31
    int en = (tid & 7) * 4;          // epilogue/reduce col base
    int eb = mbase + em;
    int egc = nbase + en;

    for (int t = 0; t < Tn; t++) {
        // ---- prefetch xp_t (independent of h) ----
        float4 xv;
        if (layer == 0) {
            int xi = x[(size_t)eb * Tn + t];
            xv = *reinterpret_cast<const float4*>(xp + (size_t)xi * Hn + egc);
        } else {
            xv = *reinterpret_cast<const float4*>(xp + ((size_t)t * Bn + eb) * Hn + egc);
        }

        float outv[4] = {0.f, 0.f, 0.f, 0.f};

        if (t > 0) {
            const bf16* hph = hseq_hi + (size_t)(t - 1) * Bn * Hn;
            const bf16* hpl = hseq_lo + (size_t)(t - 1) * Bn * Hn;
            float acc[2][4][4] = {};

            for (int half = 0; half < 2; half++) {
                // stage A half: 32 rows x 512 k, hi+lo
                for (int i = tid; i < 2048; i += 256) {
                    int r = i >> 6, c = i & 63, ch = c >> 3, off = (c & 7) * 8;
                    size_t gsrc = (size_t)(mbase + r) * Hn + half * 512 + ch * 64 + off;
                    *reinterpret_cast<uint4*>(&sAh[ch * CH + r * 72 + off]) =
                        *reinterpret_cast<const uint4*>(hph + gsrc);
                    *reinterpret_cast<uint4*>(&sAl[ch * CH + r * 72 + off]) =
                        *reinterpret_cast<const uint4*>(hpl + gsrc);
                }
                __syncthreads();

                const bf16* Ah = sAh + warp * CH;
                const bf16* Al = sAl + warp * CH;
                const bf16* Wh = sWh + (half * 8 + warp) * CH;
                const bf16* Wl = sWl + (half * 8 + warp) * CH;

#pragma unroll
                for (int kk = 0; kk < 64; kk += 16) {
                    int klo = kk + 2 * tq, khi = klo + 8;
                    uint32_t ah[2][4], al[2][4];
#pragma unroll
                    for (int mt = 0; mt < 2; mt++) {
                        int r0 = mt * 16 + g;
                        ah[mt][0] = ldsm32(&Ah[r0 * 72 + klo]);
                        ah[mt][1] = ldsm32(&Ah[(r0 + 8) * 72 + klo]);
                        ah[mt][2] = ldsm32(&Ah[r0 * 72 + khi]);
                        ah[mt][3] = ldsm32(&Ah[(r0 + 8) * 72 + khi]);
                        al[mt][0] = ldsm32(&Al[r0 * 72 + klo]);
                        al[mt][1] = ldsm32(&Al[(r0 + 8) * 72 + klo]);
                        al[mt][2] = ldsm32(&Al[r0 * 72 + khi]);
                        al[mt][3] = ldsm32(&Al[(r0 + 8) * 72 + khi]);
                    }
#pragma unroll
                    for (int j = 0; j < 4; j++) {
                        int br = j * 8 + g;
                        uint32_t bh0 = ldsm32(&Wh[br * 72 + klo]);
                        uint32_t bh1 = ldsm32(&Wh[br * 72 + khi]);
                        uint32_t bl0 = ldsm32(&Wl[br * 72 + klo]);
                        uint32_t bl1 = ldsm32(&Wl[br * 72 + khi]);
#pragma unroll
                        for (int mt = 0; mt < 2; mt++) {
                            mma_bf16(acc[mt][j], ah[mt][0], ah[mt][1], ah[mt][2], ah[mt][3], bh0, bh1);
                            mma_bf16(acc[mt][j], ah[mt][0], ah[mt][1], ah[mt][2], ah[mt][3], bl0, bl1);
                            mma_bf16(acc[mt][j], al[mt][0], al[mt][1], al[mt][2], al[mt][3], bh0, bh1);
                        }
                    }
                }
                __syncthreads();
            }

            // ---- store K-partials, 8-way reduce ----
#pragma unroll
            for (int mt = 0; mt < 2; mt++)
#pragma unroll
                for (int j = 0; j < 4; j++) {
                    int r0 = mt * 16 + g, cc = j * 8 + 2 * tq;
                    *reinterpret_cast<float2*>(&sRed[warp * 1028 + r0 * 32 + cc]) =
                        make_float2(acc[mt][j][0], acc[mt][j][1]);
                    *reinterpret_cast<float2*>(&sRed[warp * 1028 + (r0 + 8) * 32 + cc]) =
                        make_float2(acc[mt][j][2], acc[mt][j][3]);
                }
            __syncthreads();
#pragma unroll
            for (int w = 0; w < 8; w++) {
                float4 p = *reinterpret_cast<const float4*>(&sRed[w * 1028 + em * 32 + en]);
                outv[0] += p.x; outv[1] += p.y; outv[2] += p.z; outv[3] += p.w;
            }
        }

        // ---- epilogue: tanh(gemm + xp), split, store ----
        float xa[4] = {xv.x, xv.y, xv.z, xv.w};
        union { uint2 u; bf16 b[4]; } ph, pl;
#pragma unroll
        for (int i = 0; i < 4; i++) {
            float v = tanhf(outv[i] + xa[i]);
            bf16 h = __float2bfloat16(v);
            ph.b[i] = h;
            pl.b[i] = __float2bfloat16(v - __bfloat162float(h));
        }
        size_t o = (size_t)t * Bn * Hn + (size_t)eb * Hn + egc;
        *reinterpret_cast<uint2*>(hseq_hi + o) = ph.u;
        *reinterpret_cast<uint2*>(hseq_lo + o) = pl.u;

        // ---- grid barrier (monotonic, volatile-load polling) ----
        __threadfence();
        __syncthreads();
        if (tid == 0) {
            unsigned target = gen0 + (unsigned)t + 1u;
            unsigned old = atomicAdd(&g_bar_cnt, 1u);
            if (old == target * (unsigned)SCAN_CTAS - 1u) {
                atomicExch(&g_bar_gen, target);
            } else {
                while (*(volatile unsigned*)&g_bar_gen - gen0 < (unsigned)t + 1u)
                    __nanosleep(32);
            }
        }
        __syncthreads();
    }
}

// ------------------------- big parallel GEMM (split-bf16 x3) ------------
__global__ void __launch_bounds__(256) gemm_split_kernel(
    const bf16* __restrict__ Ahi, const bf16* __restrict__ Alo,
    const bf16* __restrict__ Whi, const bf16* __restrict__ Wlo,
    const float* __restrict__ bias, float* __restrict__ outf, int mode)
{
    __shared__ bf16 sAh[64][72], sAl[64][72], sWh[64][72], sWl[64][72];
    int tid = threadIdx.x, lane = tid & 31, warp = tid >> 5;
    int wm = warp & 3, wn = warp >> 2;
    int mbase = blockIdx.x * 64, nbase = blockIdx.y * 64;
    int g = lane >> 2, tq = lane & 3;
    float c[4][4] = {};

    for (int k0 = 0; k0 < Hn; k0 += 64) {
#pragma unroll
        for (int i = 0; i < 2; i++) {
            int idx = tid + i * 256;
            int r = idx >> 3, c4 = (idx & 7) * 8;
            *reinterpret_cast<uint4*>(&sAh[r][c4]) =
                *reinterpret_cast<const uint4*>(Ahi + (size_t)(mbase + r) * Hn + k0 + c4);
            *reinterpret_cast<uint4*>(&sAl[r][c4]) =
                *reinterpret_cast<const uint4*>(Alo + (size_t)(mbase + r) * Hn + k0 + c4);
            *reinterpret_cast<uint4*>(&sWh[r][c4]) =
                *reinterpret_cast<const uint4*>(Whi + (size_t)(nbase + r) * Hn + k0 + c4);
            *reinterpret_cast<uint4*>(&sWl[r][c4]) =
                *reinterpret_cast<const uint4*>(Wlo + (size_t)(nbase + r) * Hn + k0 + c4);
        }
        __syncthreads();
#pragma unroll
        for (int kk = 0; kk < 64; kk += 16) {
            int ar = wm * 16 + g;
            uint32_t ah0 = ldsm32(&sAh[ar][kk + 2 * tq]);
            uint32_t ah1 = ldsm32(&sAh[ar + 8][kk + 2 * tq]);
            uint32_t ah2 = ldsm32(&sAh[ar][kk + 2 * tq + 8]);
            uint32_t ah3 = ldsm32(&sAh[ar + 8][kk + 2 * tq + 8]);
            uint32_t al0 = ldsm32(&sAl[ar][kk + 2 * tq]);
            uint32_t al1 = ldsm32(&sAl[ar + 8][kk + 2 * tq]);
            uint32_t al2 = ldsm32(&sAl[ar][kk + 2 * tq + 8]);
            uint32_t al3 = ldsm32(&sAl[ar + 8][kk + 2 * tq + 8]);
#pragma unroll
            for (int j = 0; j < 4; j++) {
                int br = wn * 32 + j * 8 + g;
                uint32_t bh0 = ldsm32(&sWh[br][kk + 2 * tq]);
                uint32_t bh1 = ldsm32(&sWh[br][kk + 2 * tq + 8]);
                uint32_t bl0 = ldsm32(&sWl[br][kk + 2 * tq]);
                uint32_t bl1 = ldsm32(&sWl[br][kk + 2 * tq + 8]);
                mma_bf16(c[j], ah0, ah1, ah2, ah3, bh0, bh1);
                mma_bf16(c[j], ah0, ah1, ah2, ah3, bl0, bl1);
                mma_bf16(c[j], al0, al1, al2, al3, bh0, bh1);
            }
        }
        __syncthreads();
    }

#pragma unroll
    for (int j = 0; j < 4; j++) {
#pragma unroll
        for (int rh = 0; rh < 2; rh++) {
            int m = mbase + wm * 16 + g + rh * 8;
            int n = nbase + wn * 32 + j * 8 + 2 * tq;
            float v0 = c[j][rh * 2 + 0] + bias[n];
            float v1 = c[j][rh * 2 + 1] + bias[n + 1];
            if (mode == 0) {
                outf[(size_t)m * Hn + n] = v0;
                outf[(size_t)m * Hn + n + 1] = v1;
            } else {
                int b = m & (Bn - 1), t = m >> 7;
                size_t o = ((size_t)b * Tn + t) * Vn + n;
                outf[o] = v0;
                outf[o + 1] = v1;
            }
        }
    }
}

// ------------------------- layernorm + split ----------------------------
__global__ void __launch_bounds__(256) ln_kernel(
    const bf16* __restrict__ hhi, const bf16* __restrict__ hlo,
    const float* __restrict__ gam, const float* __restrict__ bet,
    bf16* __restrict__ nhi, bf16* __restrict__ nlo)
{
    __shared__ float red[18];
    size_t row = blockIdx.x;
    int tid = threadIdx.x;
    const bf16* ph = hhi + row * Hn;
    const bf16* pl = hlo + row * Hn;
    int c0 = tid * 4;
    float v[4];
    float s = 0.f, q = 0.f;
#pragma unroll
    for (int i = 0; i < 4; i++) {
        v[i] = __bfloat162float(ph[c0 + i]) + __bfloat162float(pl[c0 + i]);
        s += v[i];
        q += v[i] * v[i];
    }
#pragma unroll
    for (int o = 16; o; o >>= 1) {
        s += __shfl_xor_sync(0xffffffffu, s, o);
        q += __shfl_xor_sync(0xffffffffu, q, o);
    }
    int warp = tid >> 5, lane = tid & 31;
    if (lane == 0) { red[warp] = s; red[warp + 8] = q; }
    __syncthreads();
    if (tid == 0) {
        float ss = 0.f, qq = 0.f;
#pragma unroll
        for (int i = 0; i < 8; i++) { ss += red[i]; qq += red[i + 8]; }
        float mu = ss / (float)Hn;
        float var = qq / (float)Hn - mu * mu;
        red[16] = mu;
        red[17] = rsqrtf(var + 1e-5f);
    }
    __syncthreads();
    float mu = red[16], rstd = red[17];
#pragma unroll
    for (int i = 0; i < 4; i++) {
        float nv = (v[i] - mu) * rstd * gam[c0 + i] + bet[c0 + i];
        bf16 h = __float2bfloat16(nv);
        nhi[row * Hn + c0 + i] = h;
        nlo[row * Hn + c0 + i] = __float2bfloat16(nv - __bfloat162float(h));
    }
}

// ------------------------- launch ---------------------------------------
extern "C" void kernel_launch(void* const* d_in, const int* in_sizes, int n_in,
                              void* d_out, int out_size)
{
    const float* emb    = (const float*)d_in[0];
    const float* wi0    = (const float*)d_in[1];
    const float* bi0    = (const float*)d_in[2];
    const float* wh0    = (const float*)d_in[3];
    const float* wi1    = (const float*)d_in[4];
    const float* bi1    = (const float*)d_in[5];
    const float* wh1    = (const float*)d_in[6];
    const float* ln_g   = (const float*)d_in[7];
    const float* ln_b   = (const float*)d_in[8];
    const float* proj_w = (const float*)d_in[9];
    const float* proj_b = (const float*)d_in[10];
    const int*   x      = (const int*)d_in[11];

    bf16 *h1h, *h1l, *h2h, *h2l, *nmh, *nml;
    bf16 *wh0h, *wh0l, *wh1h, *wh1l, *wi1h, *wi1l, *pwh, *pwl;
    float *xp1, *xpe;
    cudaGetSymbolAddress((void**)&h1h,  g_h1_hi);
    cudaGetSymbolAddress((void**)&h1l,  g_h1_lo);
    cudaGetSymbolAddress((void**)&h2h,  g_h2_hi);
    cudaGetSymbolAddress((void**)&h2l,  g_h2_lo);
    cudaGetSymbolAddress((void**)&nmh,  g_nm_hi);
    cudaGetSymbolAddress((void**)&nml,  g_nm_lo);
    cudaGetSymbolAddress((void**)&wh0h, g_wh0h);
    cudaGetSymbolAddress((void**)&wh0l, g_wh0l);
    cudaGetSymbolAddress((void**)&wh1h, g_wh1h);
    cudaGetSymbolAddress((void**)&wh1l, g_wh1l);
    cudaGetSymbolAddress((void**)&wi1h, g_wi1h);
    cudaGetSymbolAddress((void**)&wi1l, g_wi1l);
    cudaGetSymbolAddress((void**)&pwh,  g_pwh);
    cudaGetSymbolAddress((void**)&pwl,  g_pwl);
    cudaGetSymbolAddress((void**)&xp1,  g_xp1);
    cudaGetSymbolAddress((void**)&xpe,  g_xpe);

    cudaFuncSetAttribute(scan_persist_kernel,
                         cudaFuncAttributeMaxDynamicSharedMemorySize,
                         SCAN_SMEM_BYTES);

    split_kernel<<<(Hn * Hn + 255) / 256, 256>>>(wh0, wh0h, wh0l, Hn * Hn);
    split_kernel<<<(Hn * Hn + 255) / 256, 256>>>(wh1, wh1h, wh1l, Hn * Hn);
    split_kernel<<<(Hn * Hn + 255) / 256, 256>>>(wi1, wi1h, wi1l, Hn * Hn);
    split_kernel<<<(Vn * Hn + 255) / 256, 256>>>(proj_w, pwh, pwl, Vn * Hn);

    xpe_kernel<<<dim3(16, 16), 256>>>(emb, wi0, bi0, xpe);

    scan_persist_kernel<<<dim3(32, 4), 256, SCAN_SMEM_BYTES>>>(
        wh0h, wh0l, h1h, h1l, xpe, x, 0);

    gemm_split_kernel<<<dim3(1024, 16), 256>>>(h1h, h1l, wi1h, wi1l, bi1, xp1, 0);

    scan_persist_kernel<<<dim3(32, 4), 256, SCAN_SMEM_BYTES>>>(
        wh1h, wh1l, h2h, h2l, xp1, x, 1);

    ln_kernel<<<Tn * Bn, 256>>>(h2h, h2l, ln_g, ln_b, nmh, nml);

    gemm_split_kernel<<<dim3(1024, 4), 256>>>(nmh, nml, pwh, pwl, proj_b, (float*)d_out, 1);
}